// round 13
// baseline (speedup 1.0000x reference)
#include <cuda_runtime.h>
#include <cuda_fp16.h>

#define B_  4
#define Q_  10000
#define H_  8
#define D_  32
#define L_  4
#define P_  4
#define S_  21760
#define BQH (B_ * Q_ * H_)

// Padded fp16 mirror, head-major. ALL levels stored twice (parity mirrors,
// shifted one pixel) so every bilinear x-pair reads one aligned 128B line.
//   L0 m0/m1: 130x132 = 17160 @ 0     / 17160   (wq=132)
//   L1 m0/m1:  66x68  = 4488  @ 34320 / 38808   (wq=68)
//   L2 m0/m1:  34x36  = 1224  @ 43296 / 44520   (wq=36)
//   L3 m0/m1:  18x20  = 360   @ 45744 / 46104   (wq=20)
// Mirror m slot j holds original pixel x = j-1-m; unwritten slots stay zero
// (device globals zero-initialized, never written) -> matches grid_sample
// zero padding exactly.
#define PIX_TOT 46464

__device__ uint4 g_vh[(size_t)B_ * H_ * PIX_TOT * 4];   // 95.2 MB

// ---------------------------------------------------------------------------
// Pre-pass over batches [b0, ...): value [B,S,H,D] fp32 -> padded fp16
// mirrors (both parities, all levels). One thread per 8 channels.
// Grid is exact -> no bounds guard.
// ---------------------------------------------------------------------------
__global__ __launch_bounds__(256)
void convert_kernel(const float* __restrict__ value, int b0)
{
    const int idx = blockIdx.x * blockDim.x + threadIdx.x;

    const int dg  = idx & 3;            // 8-channel group
    const int s   = (idx >> 2) % S_;
    const int bhl = (idx >> 2) / S_;    // local bh within this chunk
    const int h   = bhl & (H_ - 1);
    const int b   = b0 + (bhl >> 3);
    const int bh  = b * H_ + h;

    const float* src = value + (((size_t)b * S_ + s) * H_ + h) * D_ + dg * 8;
    const float4 v0 = __ldcs(reinterpret_cast<const float4*>(src));
    const float4 v1 = __ldcs(reinterpret_cast<const float4*>(src + 4));

    uint4 packed;
    {
        __half2 a = __floats2half2_rn(v0.x, v0.y);
        __half2 c = __floats2half2_rn(v0.z, v0.w);
        __half2 e = __floats2half2_rn(v1.x, v1.y);
        __half2 f = __floats2half2_rn(v1.z, v1.w);
        packed.x = *reinterpret_cast<const unsigned*>(&a);
        packed.y = *reinterpret_cast<const unsigned*>(&c);
        packed.z = *reinterpret_cast<const unsigned*>(&e);
        packed.w = *reinterpret_cast<const unsigned*>(&f);
    }

    const size_t bhbase = (size_t)bh * PIX_TOT;

    int p0, p1;
    if (s < 16384)      { int t = s;         int r = t >> 7, c = t & 127;
                          p0 = 0     + (r + 1) * 132 + c + 1;
                          p1 = 17160 + (r + 1) * 132 + c + 2; }
    else if (s < 20480) { int t = s - 16384; int r = t >> 6, c = t & 63;
                          p0 = 34320 + (r + 1) * 68 + c + 1;
                          p1 = 38808 + (r + 1) * 68 + c + 2; }
    else if (s < 21504) { int t = s - 20480; int r = t >> 5, c = t & 31;
                          p0 = 43296 + (r + 1) * 36 + c + 1;
                          p1 = 44520 + (r + 1) * 36 + c + 2; }
    else                { int t = s - 21504; int r = t >> 4, c = t & 15;
                          p0 = 45744 + (r + 1) * 20 + c + 1;
                          p1 = 46104 + (r + 1) * 20 + c + 2; }

    g_vh[(bhbase + p0) * 4 + dg] = packed;
    g_vh[(bhbase + p1) * 4 + dg] = packed;
}

// ---------------------------------------------------------------------------
// Main kernel (batch-range chunk). One warp per (b,q,h), (b,q,h)-major.
// Lane map: bits3-4 = sample slot sm, bit2 = x-corner cx, bits0-1 = dg.
// All levels parity-aligned -> 32 L1 wavefronts/warp (the fp16 floor).
// ---------------------------------------------------------------------------
__device__ __forceinline__ __half2 u2h2(unsigned u) {
    return *reinterpret_cast<const __half2*>(&u);
}

__device__ __forceinline__ __half2 h2shfl_xor(__half2 v, int ofs) {
    unsigned u = *reinterpret_cast<unsigned*>(&v);
    u = __shfl_xor_sync(0xffffffffu, u, ofs);
    return u2h2(u);
}

struct Meta {
    int offA;           // uint4 offset of row y0 (row y0+1 = compile-time imm)
    __half2 c0, c1;     // broadcast weights
};

template <int LVL>
__device__ __forceinline__ Meta level_meta(float locv, float awv,
                                           int sm, int cx, float ax, float bx)
{
    constexpr int HHs[L_]   = {128, 64, 32, 16};
    constexpr int WWs[L_]   = {128, 64, 32, 16};
    constexpr int BASEs[L_] = {0, 34320, 43296, 45744};
    constexpr int MSs[L_]   = {17161, 4489, 1225, 361};   // mirror size + 1
    constexpr int WQs[L_]   = {132, 68, 36, 20};

    const float xl = __shfl_sync(0xffffffffu, locv, 8 * LVL + 2 * sm);
    const float yl = __shfl_sync(0xffffffffu, locv, 8 * LVL + 2 * sm + 1);
    const float wa = __shfl_sync(0xffffffffu, awv,  4 * LVL + sm);

    const float x = fmaf(xl, (float)WWs[LVL], -0.5f);
    const float y = fmaf(yl, (float)HHs[LVL], -0.5f);
    const int ix0 = __float2int_rd(x);
    const int iy0 = __float2int_rd(y);
    const float fx = x - (float)ix0;
    const float fy = y - (float)iy0;

    const float cwx = fmaf(fx, ax, bx) * wa;
    const float cw1 = cwx * fy;
    const float cw0 = cwx - cw1;

    const int m = (ix0 & 1) ^ 1;        // parity mirror: base slot even
    const int pix = BASEs[LVL] + m * MSs[LVL]
                  + (iy0 + 1) * WQs[LVL] + ix0 + 1 + cx;

    Meta r;
    r.offA = pix * 4;
    r.c0 = __float2half2_rn(cw0);
    r.c1 = __float2half2_rn(cw1);
    return r;
}

template <int LVL, bool FIRST>
__device__ __forceinline__ void do_level(const uint4* __restrict__ base,
                                         const Meta& m,
                                         __half2& p0, __half2& p1,
                                         __half2& p2, __half2& p3)
{
    constexpr int WQs[L_] = {132, 68, 36, 20};
    const uint4* pa = base + m.offA;
    const uint4 rA = pa[0];
    const uint4 rB = pa[WQs[LVL] * 4];   // compile-time immediate offset

    if (FIRST) {
        p0 = __hmul2(u2h2(rA.x), m.c0);
        p1 = __hmul2(u2h2(rA.y), m.c0);
        p2 = __hmul2(u2h2(rA.z), m.c0);
        p3 = __hmul2(u2h2(rA.w), m.c0);
    } else {
        p0 = __hfma2(u2h2(rA.x), m.c0, p0);
        p1 = __hfma2(u2h2(rA.y), m.c0, p1);
        p2 = __hfma2(u2h2(rA.z), m.c0, p2);
        p3 = __hfma2(u2h2(rA.w), m.c0, p3);
    }
    p0 = __hfma2(u2h2(rB.x), m.c1, p0);
    p1 = __hfma2(u2h2(rB.y), m.c1, p1);
    p2 = __hfma2(u2h2(rB.z), m.c1, p2);
    p3 = __hfma2(u2h2(rB.w), m.c1, p3);
}

__global__ __launch_bounds__(256)
void msda_kernel(const float* __restrict__ loc,
                 const float* __restrict__ aw,
                 float* __restrict__ out,
                 int wbase)
{
    const int warp = wbase + ((blockIdx.x * blockDim.x + threadIdx.x) >> 5);
    const int lane = threadIdx.x & 31;

    const int h  = warp & (H_ - 1);
    const int bq = warp >> 3;
    const int b  = bq / Q_;

    const float locv = __ldcs(loc + (size_t)warp * (L_ * P_ * 2) + lane);
    const float awv  = (lane < L_ * P_)
                     ? __ldcs(aw + (size_t)warp * (L_ * P_) + lane) : 0.0f;

    const int sm = lane >> 3;
    const int cx = (lane >> 2) & 1;
    const int dg = lane & 3;

    const float ax = cx ? 1.0f : -1.0f;
    const float bx = cx ? 0.0f : 1.0f;

    const uint4* base = g_vh + ((size_t)(b * H_ + h)) * (PIX_TOT * 4) + dg;

    // Group 0: levels 0,1 in half2 partials g0-3.
    __half2 g0, g1, g2, g3;
    {
        const Meta m0 = level_meta<0>(locv, awv, sm, cx, ax, bx);
        do_level<0, true >(base, m0, g0, g1, g2, g3);
        const Meta m1 = level_meta<1>(locv, awv, sm, cx, ax, bx);
        do_level<1, false>(base, m1, g0, g1, g2, g3);
    }

    // Group 1: levels 2,3 in half2 partials p0-3.
    __half2 p0, p1, p2, p3;
    {
        const Meta m2 = level_meta<2>(locv, awv, sm, cx, ax, bx);
        do_level<2, true >(base, m2, p0, p1, p2, p3);
        const Meta m3 = level_meta<3>(locv, awv, sm, cx, ax, bx);
        do_level<3, false>(base, m3, p0, p1, p2, p3);
    }

    // Combine groups (half2).
    p0 = __hadd2(p0, g0);
    p1 = __hadd2(p1, g1);
    p2 = __hadd2(p2, g2);
    p3 = __hadd2(p3, g3);

    // Corner (xor 4) and first sample stage (xor 8), packed in half2.
#pragma unroll
    for (int ofs = 4; ofs <= 8; ofs <<= 1) {
        p0 = __hadd2(p0, h2shfl_xor(p0, ofs));
        p1 = __hadd2(p1, h2shfl_xor(p1, ofs));
        p2 = __hadd2(p2, h2shfl_xor(p2, ofs));
        p3 = __hadd2(p3, h2shfl_xor(p3, ofs));
    }

    // To fp32 once.
    float accf[8];
    {
        float2 t;
        t = __half22float2(p0); accf[0] = t.x; accf[1] = t.y;
        t = __half22float2(p1); accf[2] = t.x; accf[3] = t.y;
        t = __half22float2(p2); accf[4] = t.x; accf[5] = t.y;
        t = __half22float2(p3); accf[6] = t.x; accf[7] = t.y;
    }

    // Final sample stage (xor 16) in fp32.
#pragma unroll
    for (int i = 0; i < 8; i++)
        accf[i] += __shfl_xor_sync(0xffffffffu, accf[i], 16);

    if (lane < 4) {
        float* o = out + (size_t)warp * D_ + dg * 8;
        __stcs(reinterpret_cast<float4*>(o),
               make_float4(accf[0], accf[1], accf[2], accf[3]));
        __stcs(reinterpret_cast<float4*>(o + 4),
               make_float4(accf[4], accf[5], accf[6], accf[7]));
    }
}

// ---------------------------------------------------------------------------
// Launch: asymmetric 2-chunk pipeline.
//   s_conv (LOW):  conv{b0}(~7us)  conv{b1,2,3}(~21us)
//   s_main (HIGH):        msda{b0}(~28us)   msda{b1,2,3}(~71us)
// conv123 hides fully under msda0. Streams/events created lazily on the
// first (pre-capture) call; captured work identical every call.
// ---------------------------------------------------------------------------
extern "C" void kernel_launch(void* const* d_in, const int* in_sizes, int n_in,
                              void* d_out, int out_size)
{
    const float* value = (const float*)d_in[0];
    const float* loc   = (const float*)d_in[3];
    const float* aw    = (const float*)d_in[4];
    float* out = (float*)d_out;

    static cudaStream_t s_conv = nullptr, s_main = nullptr;
    static cudaEvent_t evs = nullptr, evj = nullptr;
    static cudaEvent_t evc0 = nullptr, evc123 = nullptr;
    if (s_conv == nullptr) {
        int lo, hi;   // lo = least priority (numerically greatest)
        cudaDeviceGetStreamPriorityRange(&lo, &hi);
        cudaStreamCreateWithPriority(&s_conv, cudaStreamNonBlocking, lo);
        cudaStreamCreateWithPriority(&s_main, cudaStreamNonBlocking, hi);
        cudaEventCreateWithFlags(&evs,    cudaEventDisableTiming);
        cudaEventCreateWithFlags(&evj,    cudaEventDisableTiming);
        cudaEventCreateWithFlags(&evc0,   cudaEventDisableTiming);
        cudaEventCreateWithFlags(&evc123, cudaEventDisableTiming);
    }

    const int conv_grid_b = (H_ * S_ * (D_ / 8)) / 256;  // 2720 per batch
    const int main_grid_b = (Q_ * H_ * 32) / 256;        // 10000 per batch

    // Fork both side streams from the legacy stream.
    cudaEventRecord(evs, (cudaStream_t)0);
    cudaStreamWaitEvent(s_conv, evs, 0);
    cudaStreamWaitEvent(s_main, evs, 0);

    // Chunk 0: batch 0.
    convert_kernel<<<conv_grid_b, 256, 0, s_conv>>>(value, 0);
    cudaEventRecord(evc0, s_conv);
    cudaStreamWaitEvent(s_main, evc0, 0);
    msda_kernel<<<main_grid_b, 256, 0, s_main>>>(loc, aw, out, 0);

    // Chunk 1: batches 1..3 (convert hides under msda chunk 0).
    convert_kernel<<<3 * conv_grid_b, 256, 0, s_conv>>>(value, 1);
    cudaEventRecord(evc123, s_conv);
    cudaStreamWaitEvent(s_main, evc123, 0);
    msda_kernel<<<3 * main_grid_b, 256, 0, s_main>>>(loc, aw, out, Q_ * H_);

    // Join back to the legacy stream.
    cudaEventRecord(evj, s_main);
    cudaStreamWaitEvent((cudaStream_t)0, evj, 0);
}

// round 14
// speedup vs baseline: 1.0389x; 1.0389x over previous
#include <cuda_runtime.h>
#include <cuda_fp16.h>

#define B_  4
#define Q_  10000
#define H_  8
#define D_  32
#define L_  4
#define P_  4
#define S_  21760
#define BQH (B_ * Q_ * H_)

// Padded fp16 mirror, head-major (R12 layout — 59.5MB, comfortably L2-
// resident; the 95MB all-levels-duplicated variant regressed via DRAM).
// Levels 1-3 stored twice (parity mirrors, shifted one pixel) so their
// bilinear x-pair reads one aligned 128B line. L0 single copy.
//   L0:        130x130 = 16900 @ 0            (wq=130)
//   L1 m0/m1:  66x68   = 4488  @ 16900/21388  (wq=68)
//   L2 m0/m1:  34x36   = 1224  @ 25876/27100  (wq=36)
//   L3 m0/m1:  18x20   = 360   @ 28324/28684  (wq=20)
// Unwritten slots stay zero (device globals zero-initialized, never written)
// -> matches grid_sample zero padding exactly.
#define PIX_TOT 29044

__device__ uint4 g_vh[(size_t)B_ * H_ * PIX_TOT * 4];   // 59.5 MB

// ---------------------------------------------------------------------------
// Pre-pass over batches [b0, ...): value [B,S,H,D] fp32 -> padded fp16
// mirrors. One thread per 8 channels: 32B streamed read, 16B store.
// Grid is exact -> no bounds guard.
// ---------------------------------------------------------------------------
__global__ __launch_bounds__(256)
void convert_kernel(const float* __restrict__ value, int b0)
{
    const int idx = blockIdx.x * blockDim.x + threadIdx.x;

    const int dg  = idx & 3;            // 8-channel group
    const int s   = (idx >> 2) % S_;
    const int bhl = (idx >> 2) / S_;    // local bh within this chunk
    const int h   = bhl & (H_ - 1);
    const int b   = b0 + (bhl >> 3);
    const int bh  = b * H_ + h;

    const float* src = value + (((size_t)b * S_ + s) * H_ + h) * D_ + dg * 8;
    const float4 v0 = __ldcs(reinterpret_cast<const float4*>(src));
    const float4 v1 = __ldcs(reinterpret_cast<const float4*>(src + 4));

    uint4 packed;
    {
        __half2 a = __floats2half2_rn(v0.x, v0.y);
        __half2 c = __floats2half2_rn(v0.z, v0.w);
        __half2 e = __floats2half2_rn(v1.x, v1.y);
        __half2 f = __floats2half2_rn(v1.z, v1.w);
        packed.x = *reinterpret_cast<const unsigned*>(&a);
        packed.y = *reinterpret_cast<const unsigned*>(&c);
        packed.z = *reinterpret_cast<const unsigned*>(&e);
        packed.w = *reinterpret_cast<const unsigned*>(&f);
    }

    const size_t bhbase = (size_t)bh * PIX_TOT;

    int p0, p1 = -1;
    if (s < 16384)      { int t = s;         int r = t >> 7, c = t & 127;
                          p0 = 0     + (r + 1) * 130 + c + 1; }
    else if (s < 20480) { int t = s - 16384; int r = t >> 6, c = t & 63;
                          p0 = 16900 + (r + 1) * 68 + c + 1;
                          p1 = 21388 + (r + 1) * 68 + c + 2; }
    else if (s < 21504) { int t = s - 20480; int r = t >> 5, c = t & 31;
                          p0 = 25876 + (r + 1) * 36 + c + 1;
                          p1 = 27100 + (r + 1) * 36 + c + 2; }
    else                { int t = s - 21504; int r = t >> 4, c = t & 15;
                          p0 = 28324 + (r + 1) * 20 + c + 1;
                          p1 = 28684 + (r + 1) * 20 + c + 2; }

    g_vh[(bhbase + p0) * 4 + dg] = packed;
    if (p1 >= 0) g_vh[(bhbase + p1) * 4 + dg] = packed;
}

// ---------------------------------------------------------------------------
// Main kernel (batch-range chunk). One warp per (b,q,h), (b,q,h)-major.
// Lane map: bits3-4 = sample slot sm, bit2 = x-corner cx, bits0-1 = dg.
// Tail: xor4 + xor8 packed in half2, single cvt, xor16 in fp32.
// ---------------------------------------------------------------------------
__device__ __forceinline__ __half2 u2h2(unsigned u) {
    return *reinterpret_cast<const __half2*>(&u);
}

__device__ __forceinline__ __half2 h2shfl_xor(__half2 v, int ofs) {
    unsigned u = *reinterpret_cast<unsigned*>(&v);
    u = __shfl_xor_sync(0xffffffffu, u, ofs);
    return u2h2(u);
}

struct Meta {
    int offA;           // uint4 offset of row y0 (row y0+1 = compile-time imm)
    __half2 c0, c1;     // broadcast weights
};

template <int LVL>
__device__ __forceinline__ Meta level_meta(float locv, float awv,
                                           int sm, int cx, float ax, float bx)
{
    constexpr int HHs[L_]   = {128, 64, 32, 16};
    constexpr int WWs[L_]   = {128, 64, 32, 16};
    constexpr int BASEs[L_] = {0, 16900, 25876, 28324};
    constexpr int MSs[L_]   = {0, 4489, 1225, 361};   // mirror stride + 1
    constexpr int WQs[L_]   = {130, 68, 36, 20};

    const float xl = __shfl_sync(0xffffffffu, locv, 8 * LVL + 2 * sm);
    const float yl = __shfl_sync(0xffffffffu, locv, 8 * LVL + 2 * sm + 1);
    const float wa = __shfl_sync(0xffffffffu, awv,  4 * LVL + sm);

    const float x = fmaf(xl, (float)WWs[LVL], -0.5f);
    const float y = fmaf(yl, (float)HHs[LVL], -0.5f);
    const int ix0 = __float2int_rd(x);
    const int iy0 = __float2int_rd(y);
    const float fx = x - (float)ix0;
    const float fy = y - (float)iy0;

    const float cwx = fmaf(fx, ax, bx) * wa;
    const float cw1 = cwx * fy;
    const float cw0 = cwx - cw1;

    const int m = (LVL == 0) ? 0 : ((ix0 & 1) ^ 1);
    const int pix = BASEs[LVL] + m * MSs[LVL]
                  + (iy0 + 1) * WQs[LVL] + ix0 + 1 + cx;

    Meta r;
    r.offA = pix * 4;
    r.c0 = __float2half2_rn(cw0);
    r.c1 = __float2half2_rn(cw1);
    return r;
}

template <int LVL, bool FIRST>
__device__ __forceinline__ void do_level(const uint4* __restrict__ base,
                                         const Meta& m,
                                         __half2& p0, __half2& p1,
                                         __half2& p2, __half2& p3)
{
    constexpr int WQs[L_] = {130, 68, 36, 20};
    const uint4* pa = base + m.offA;
    const uint4 rA = pa[0];
    const uint4 rB = pa[WQs[LVL] * 4];   // compile-time immediate offset

    if (FIRST) {
        p0 = __hmul2(u2h2(rA.x), m.c0);
        p1 = __hmul2(u2h2(rA.y), m.c0);
        p2 = __hmul2(u2h2(rA.z), m.c0);
        p3 = __hmul2(u2h2(rA.w), m.c0);
    } else {
        p0 = __hfma2(u2h2(rA.x), m.c0, p0);
        p1 = __hfma2(u2h2(rA.y), m.c0, p1);
        p2 = __hfma2(u2h2(rA.z), m.c0, p2);
        p3 = __hfma2(u2h2(rA.w), m.c0, p3);
    }
    p0 = __hfma2(u2h2(rB.x), m.c1, p0);
    p1 = __hfma2(u2h2(rB.y), m.c1, p1);
    p2 = __hfma2(u2h2(rB.z), m.c1, p2);
    p3 = __hfma2(u2h2(rB.w), m.c1, p3);
}

__global__ __launch_bounds__(256)
void msda_kernel(const float* __restrict__ loc,
                 const float* __restrict__ aw,
                 float* __restrict__ out,
                 int wbase)
{
    const int warp = wbase + ((blockIdx.x * blockDim.x + threadIdx.x) >> 5);
    const int lane = threadIdx.x & 31;

    const int h  = warp & (H_ - 1);
    const int bq = warp >> 3;
    const int b  = bq / Q_;

    const float locv = __ldcs(loc + (size_t)warp * (L_ * P_ * 2) + lane);
    const float awv  = (lane < L_ * P_)
                     ? __ldcs(aw + (size_t)warp * (L_ * P_) + lane) : 0.0f;

    const int sm = lane >> 3;
    const int cx = (lane >> 2) & 1;
    const int dg = lane & 3;

    const float ax = cx ? 1.0f : -1.0f;
    const float bx = cx ? 0.0f : 1.0f;

    const uint4* base = g_vh + ((size_t)(b * H_ + h)) * (PIX_TOT * 4) + dg;

    // Group 0: levels 0,1 in half2 partials g0-3.
    __half2 g0, g1, g2, g3;
    {
        const Meta m0 = level_meta<0>(locv, awv, sm, cx, ax, bx);
        do_level<0, true >(base, m0, g0, g1, g2, g3);
        const Meta m1 = level_meta<1>(locv, awv, sm, cx, ax, bx);
        do_level<1, false>(base, m1, g0, g1, g2, g3);
    }

    // Group 1: levels 2,3 in half2 partials p0-3.
    __half2 p0, p1, p2, p3;
    {
        const Meta m2 = level_meta<2>(locv, awv, sm, cx, ax, bx);
        do_level<2, true >(base, m2, p0, p1, p2, p3);
        const Meta m3 = level_meta<3>(locv, awv, sm, cx, ax, bx);
        do_level<3, false>(base, m3, p0, p1, p2, p3);
    }

    // Combine groups (half2).
    p0 = __hadd2(p0, g0);
    p1 = __hadd2(p1, g1);
    p2 = __hadd2(p2, g2);
    p3 = __hadd2(p3, g3);

    // Corner (xor 4) and first sample stage (xor 8), packed in half2.
#pragma unroll
    for (int ofs = 4; ofs <= 8; ofs <<= 1) {
        p0 = __hadd2(p0, h2shfl_xor(p0, ofs));
        p1 = __hadd2(p1, h2shfl_xor(p1, ofs));
        p2 = __hadd2(p2, h2shfl_xor(p2, ofs));
        p3 = __hadd2(p3, h2shfl_xor(p3, ofs));
    }

    // To fp32 once.
    float accf[8];
    {
        float2 t;
        t = __half22float2(p0); accf[0] = t.x; accf[1] = t.y;
        t = __half22float2(p1); accf[2] = t.x; accf[3] = t.y;
        t = __half22float2(p2); accf[4] = t.x; accf[5] = t.y;
        t = __half22float2(p3); accf[6] = t.x; accf[7] = t.y;
    }

    // Final sample stage (xor 16) in fp32.
#pragma unroll
    for (int i = 0; i < 8; i++)
        accf[i] += __shfl_xor_sync(0xffffffffu, accf[i], 16);

    if (lane < 4) {
        float* o = out + (size_t)warp * D_ + dg * 8;
        __stcs(reinterpret_cast<float4*>(o),
               make_float4(accf[0], accf[1], accf[2], accf[3]));
        __stcs(reinterpret_cast<float4*>(o + 4),
               make_float4(accf[4], accf[5], accf[6], accf[7]));
    }
}

// ---------------------------------------------------------------------------
// Launch: asymmetric 2-chunk pipeline, minimal dependency edges.
//   s_main (HIGH): conv0 -> msda0 -> (wait evc123) msda123
//   s_conv (LOW):  conv123 -> record evc123
// conv0 precedes msda0 IN-STREAM (no cross-stream event). High priority makes
// conv0's 2720 blocks schedule ahead of conv123's 8160; conv123 fills idle
// slots and hides under msda0's ~29us window. Streams/events created lazily
// on the first (pre-capture) call; captured work identical every call.
// ---------------------------------------------------------------------------
extern "C" void kernel_launch(void* const* d_in, const int* in_sizes, int n_in,
                              void* d_out, int out_size)
{
    const float* value = (const float*)d_in[0];
    const float* loc   = (const float*)d_in[3];
    const float* aw    = (const float*)d_in[4];
    float* out = (float*)d_out;

    static cudaStream_t s_conv = nullptr, s_main = nullptr;
    static cudaEvent_t evs = nullptr, evj = nullptr, evc123 = nullptr;
    if (s_conv == nullptr) {
        int lo, hi;   // lo = least priority (numerically greatest)
        cudaDeviceGetStreamPriorityRange(&lo, &hi);
        cudaStreamCreateWithPriority(&s_conv, cudaStreamNonBlocking, lo);
        cudaStreamCreateWithPriority(&s_main, cudaStreamNonBlocking, hi);
        cudaEventCreateWithFlags(&evs,    cudaEventDisableTiming);
        cudaEventCreateWithFlags(&evj,    cudaEventDisableTiming);
        cudaEventCreateWithFlags(&evc123, cudaEventDisableTiming);
    }

    const int conv_grid_b = (H_ * S_ * (D_ / 8)) / 256;  // 2720 per batch
    const int main_grid_b = (Q_ * H_ * 32) / 256;        // 10000 per batch

    // Fork both side streams from the legacy stream.
    cudaEventRecord(evs, (cudaStream_t)0);
    cudaStreamWaitEvent(s_main, evs, 0);
    cudaStreamWaitEvent(s_conv, evs, 0);

    // s_conv: big convert chunk (batches 1..3), hides under msda0.
    convert_kernel<<<3 * conv_grid_b, 256, 0, s_conv>>>(value, 1);
    cudaEventRecord(evc123, s_conv);

    // s_main: conv0 then msda0 in-stream, then msda123 after conv123.
    convert_kernel<<<conv_grid_b, 256, 0, s_main>>>(value, 0);
    msda_kernel<<<main_grid_b, 256, 0, s_main>>>(loc, aw, out, 0);
    cudaStreamWaitEvent(s_main, evc123, 0);
    msda_kernel<<<3 * main_grid_b, 256, 0, s_main>>>(loc, aw, out, Q_ * H_);

    // Join back to the legacy stream.
    cudaEventRecord(evj, s_main);
    cudaStreamWaitEvent((cudaStream_t)0, evj, 0);
}